// round 9
// baseline (speedup 1.0000x reference)
#include <cuda_runtime.h>
#include <math.h>

#define B_  4
#define S_  2048
#define D_  1024
#define H_  16
#define HD_ 64
#define M_  (B_ * S_)   // 8192

// Scratch (allocation-free): Q,K,V in [B,H,S,Hd], attention output in [B,S,D]
__device__ float g_q[(size_t)B_ * H_ * S_ * HD_];
__device__ float g_k[(size_t)B_ * H_ * S_ * HD_];
__device__ float g_v[(size_t)B_ * H_ * S_ * HD_];
__device__ float g_ao[(size_t)M_ * D_];

// ---------------------------------------------------------------------------
// NT GEMM: C[m,n] = sum_k A[m,k] * W[n,k] + bias[n]
// A: [M, K] row-major, W: [N, K] row-major (torch Linear weight)
// mode 0: C row-major [M, N]
// mode 1: scatter to [B, H, S, Hd] (m = b*S+s, n = h*HD+hd)
// 128x128 tile, BK=8, 256 threads, 8x8 per thread.
// ---------------------------------------------------------------------------
__global__ __launch_bounds__(256) void gemm_nt(
    const float* __restrict__ A, const float* __restrict__ W,
    const float* __restrict__ bias, float* __restrict__ C, int mode)
{
    const int K = D_;
    __shared__ float As[8][128];
    __shared__ float Ws[8][128];

    const int tid  = threadIdx.x;
    const int bm   = blockIdx.y * 128;
    const int bn   = blockIdx.x * 128;
    const int lrow = tid >> 1;          // 0..127
    const int lk   = (tid & 1) << 2;    // 0 or 4

    const float* Aptr = A + (size_t)(bm + lrow) * K + lk;
    const float* Wptr = W + (size_t)(bn + lrow) * K + lk;

    const int ty = tid >> 4;   // 0..15 -> m sub-tile
    const int tx = tid & 15;   // 0..15 -> n sub-tile

    float acc[8][8];
#pragma unroll
    for (int i = 0; i < 8; i++)
#pragma unroll
        for (int j = 0; j < 8; j++) acc[i][j] = 0.f;

    for (int kt = 0; kt < K; kt += 8) {
        float4 a4 = *(const float4*)(Aptr + kt);
        float4 w4 = *(const float4*)(Wptr + kt);
        As[lk + 0][lrow] = a4.x; As[lk + 1][lrow] = a4.y;
        As[lk + 2][lrow] = a4.z; As[lk + 3][lrow] = a4.w;
        Ws[lk + 0][lrow] = w4.x; Ws[lk + 1][lrow] = w4.y;
        Ws[lk + 2][lrow] = w4.z; Ws[lk + 3][lrow] = w4.w;
        __syncthreads();

#pragma unroll
        for (int kk = 0; kk < 8; kk++) {
            float ar[8], br[8];
            const float4* ap = (const float4*)&As[kk][ty * 8];
            const float4* bp = (const float4*)&Ws[kk][tx * 8];
            float4 a0 = ap[0], a1 = ap[1];
            float4 b0 = bp[0], b1 = bp[1];
            ar[0]=a0.x; ar[1]=a0.y; ar[2]=a0.z; ar[3]=a0.w;
            ar[4]=a1.x; ar[5]=a1.y; ar[6]=a1.z; ar[7]=a1.w;
            br[0]=b0.x; br[1]=b0.y; br[2]=b0.z; br[3]=b0.w;
            br[4]=b1.x; br[5]=b1.y; br[6]=b1.z; br[7]=b1.w;
#pragma unroll
            for (int i = 0; i < 8; i++)
#pragma unroll
                for (int j = 0; j < 8; j++)
                    acc[i][j] = fmaf(ar[i], br[j], acc[i][j]);
        }
        __syncthreads();
    }

#pragma unroll
    for (int i = 0; i < 8; i++) {
        const int gm = bm + ty * 8 + i;
#pragma unroll
        for (int j = 0; j < 8; j++) {
            const int gn = bn + tx * 8 + j;
            const float v = acc[i][j] + bias[gn];
            if (mode == 0) {
                C[(size_t)gm * D_ + gn] = v;
            } else {
                const int b  = gm >> 11;      // / S_
                const int s  = gm & (S_ - 1);
                const int h  = gn >> 6;       // / HD_
                const int hd = gn & (HD_ - 1);
                C[((((size_t)b * H_ + h) * S_ + s) << 6) + hd] = v;
            }
        }
    }
}

// ---------------------------------------------------------------------------
// Flash attention, fp32. One CTA = (b,h) x 128 query rows; 1 thread = 1 query.
// Q row + 64-float accumulator in registers; K/V staged in smem in 64-key
// tiles, read via broadcast LDS.128. Online softmax with conditional rescale.
// Output written in [B, S, D] layout (ready for output projection).
// ---------------------------------------------------------------------------
__global__ __launch_bounds__(128) void attn_kernel(
    const float* __restrict__ Q, const float* __restrict__ Kg,
    const float* __restrict__ Vg, float* __restrict__ O)
{
    __shared__ float sK[64 * HD_];
    __shared__ float sV[64 * HD_];

    const int bh = blockIdx.y;          // 0..63
    const int b  = bh >> 4;             // / H_
    const int t  = threadIdx.x;
    const int qrow = blockIdx.x * 128 + t;

    const float* qp = Q + ((size_t)bh * S_ + qrow) * HD_;
    float4 q4[16];
#pragma unroll
    for (int i = 0; i < 16; i++) q4[i] = ((const float4*)qp)[i];

    float4 acc[16];
#pragma unroll
    for (int i = 0; i < 16; i++) acc[i] = make_float4(0.f, 0.f, 0.f, 0.f);

    float mmax = -INFINITY;
    float l = 0.f;
    const float scale = 0.125f;  // HD_^-0.5

    const float* kbase = Kg + (size_t)bh * S_ * HD_;
    const float* vbase = Vg + (size_t)bh * S_ * HD_;

    for (int k0 = 0; k0 < S_; k0 += 64) {
        // cooperative tile load: 64*64 floats = 1024 float4, 128 threads x 8
        const float4* ksrc = (const float4*)(kbase + (size_t)k0 * HD_);
        const float4* vsrc = (const float4*)(vbase + (size_t)k0 * HD_);
        float4* dk = (float4*)sK;
        float4* dv = (float4*)sV;
#pragma unroll
        for (int i = 0; i < 8; i++) {
            dk[t + i * 128] = ksrc[t + i * 128];
            dv[t + i * 128] = vsrc[t + i * 128];
        }
        __syncthreads();

#pragma unroll 2
        for (int j = 0; j < 64; j++) {
            const float4* kr = (const float4*)(sK + j * HD_);
            float s0 = 0.f, s1 = 0.f, s2 = 0.f, s3 = 0.f;
#pragma unroll
            for (int i = 0; i < 16; i++) {
                float4 kv = kr[i];
                s0 = fmaf(q4[i].x, kv.x, s0);
                s1 = fmaf(q4[i].y, kv.y, s1);
                s2 = fmaf(q4[i].z, kv.z, s2);
                s3 = fmaf(q4[i].w, kv.w, s3);
            }
            float s = ((s0 + s1) + (s2 + s3)) * scale;

            if (s > mmax) {
                const float corr = __expf(mmax - s);  // exp(-inf)=0 on first key
                mmax = s;
                l *= corr;
#pragma unroll
                for (int i = 0; i < 16; i++) {
                    acc[i].x *= corr; acc[i].y *= corr;
                    acc[i].z *= corr; acc[i].w *= corr;
                }
            }
            const float p = __expf(s - mmax);
            l += p;

            const float4* vr = (const float4*)(sV + j * HD_);
#pragma unroll
            for (int i = 0; i < 16; i++) {
                float4 vv = vr[i];
                acc[i].x = fmaf(p, vv.x, acc[i].x);
                acc[i].y = fmaf(p, vv.y, acc[i].y);
                acc[i].z = fmaf(p, vv.z, acc[i].z);
                acc[i].w = fmaf(p, vv.w, acc[i].w);
            }
        }
        __syncthreads();
    }

    const float inv = 1.f / l;
    const int h = bh & (H_ - 1);
    float* op = O + ((size_t)(b * S_ + qrow)) * D_ + h * HD_;
#pragma unroll
    for (int i = 0; i < 16; i++) {
        float4 o;
        o.x = acc[i].x * inv; o.y = acc[i].y * inv;
        o.z = acc[i].z * inv; o.w = acc[i].w * inv;
        ((float4*)op)[i] = o;
    }
}

// ---------------------------------------------------------------------------
extern "C" void kernel_launch(void* const* d_in, const int* in_sizes, int n_in,
                              void* d_out, int out_size)
{
    const float* x  = (const float*)d_in[0];
    const float* wq = (const float*)d_in[1];
    const float* bq = (const float*)d_in[2];
    const float* wk = (const float*)d_in[3];
    const float* bk = (const float*)d_in[4];
    const float* wv = (const float*)d_in[5];
    const float* bv = (const float*)d_in[6];
    const float* wo = (const float*)d_in[7];
    const float* bo = (const float*)d_in[8];
    float* out = (float*)d_out;

    float *q, *k, *v, *ao;
    cudaGetSymbolAddress((void**)&q,  g_q);
    cudaGetSymbolAddress((void**)&k,  g_k);
    cudaGetSymbolAddress((void**)&v,  g_v);
    cudaGetSymbolAddress((void**)&ao, g_ao);

    dim3 ggrid(D_ / 128, M_ / 128);   // (8, 64)
    gemm_nt<<<ggrid, 256>>>(x, wq, bq, q, 1);
    gemm_nt<<<ggrid, 256>>>(x, wk, bk, k, 1);
    gemm_nt<<<ggrid, 256>>>(x, wv, bv, v, 1);

    dim3 agrid(S_ / 128, B_ * H_);    // (16, 64)
    attn_kernel<<<agrid, 128>>>(q, k, v, ao);

    gemm_nt<<<ggrid, 256>>>(ao, wo, bo, out, 0);
}

// round 11
// speedup vs baseline: 1.0004x; 1.0004x over previous
#include <cuda_runtime.h>
#include <math.h>

#define B_  4
#define S_  2048
#define D_  1024
#define H_  16
#define HD_ 64
#define M_  (B_ * S_)   // 8192

// Scratch (allocation-free): Q,K,V in [B,H,S,Hd], attention output in [B,S,D]
__device__ float g_q[(size_t)B_ * H_ * S_ * HD_];
__device__ float g_k[(size_t)B_ * H_ * S_ * HD_];
__device__ float g_v[(size_t)B_ * H_ * S_ * HD_];
__device__ float g_ao[(size_t)M_ * D_];

// ---------------------------------------------------------------------------
// NT GEMM: C[m,n] = sum_k A[m,k] * W[n,k] + bias[n]
// A: [M, K] row-major, W: [N, K] row-major (torch Linear weight)
// mode 0: C row-major [M, N]
// mode 1: scatter to [B, H, S, Hd] (m = b*S+s, n = h*HD+hd)
// 128x128 tile, BK=8, 256 threads, 8x8 per thread.
// ---------------------------------------------------------------------------
__global__ __launch_bounds__(256) void gemm_nt(
    const float* __restrict__ A, const float* __restrict__ W,
    const float* __restrict__ bias, float* __restrict__ C, int mode)
{
    const int K = D_;
    __shared__ float As[8][128];
    __shared__ float Ws[8][128];

    const int tid  = threadIdx.x;
    const int bm   = blockIdx.y * 128;
    const int bn   = blockIdx.x * 128;
    const int lrow = tid >> 1;          // 0..127
    const int lk   = (tid & 1) << 2;    // 0 or 4

    const float* Aptr = A + (size_t)(bm + lrow) * K + lk;
    const float* Wptr = W + (size_t)(bn + lrow) * K + lk;

    const int ty = tid >> 4;   // 0..15 -> m sub-tile
    const int tx = tid & 15;   // 0..15 -> n sub-tile

    float acc[8][8];
#pragma unroll
    for (int i = 0; i < 8; i++)
#pragma unroll
        for (int j = 0; j < 8; j++) acc[i][j] = 0.f;

    for (int kt = 0; kt < K; kt += 8) {
        float4 a4 = *(const float4*)(Aptr + kt);
        float4 w4 = *(const float4*)(Wptr + kt);
        As[lk + 0][lrow] = a4.x; As[lk + 1][lrow] = a4.y;
        As[lk + 2][lrow] = a4.z; As[lk + 3][lrow] = a4.w;
        Ws[lk + 0][lrow] = w4.x; Ws[lk + 1][lrow] = w4.y;
        Ws[lk + 2][lrow] = w4.z; Ws[lk + 3][lrow] = w4.w;
        __syncthreads();

#pragma unroll
        for (int kk = 0; kk < 8; kk++) {
            float ar[8], br[8];
            const float4* ap = (const float4*)&As[kk][ty * 8];
            const float4* bp = (const float4*)&Ws[kk][tx * 8];
            float4 a0 = ap[0], a1 = ap[1];
            float4 b0 = bp[0], b1 = bp[1];
            ar[0]=a0.x; ar[1]=a0.y; ar[2]=a0.z; ar[3]=a0.w;
            ar[4]=a1.x; ar[5]=a1.y; ar[6]=a1.z; ar[7]=a1.w;
            br[0]=b0.x; br[1]=b0.y; br[2]=b0.z; br[3]=b0.w;
            br[4]=b1.x; br[5]=b1.y; br[6]=b1.z; br[7]=b1.w;
#pragma unroll
            for (int i = 0; i < 8; i++)
#pragma unroll
                for (int j = 0; j < 8; j++)
                    acc[i][j] = fmaf(ar[i], br[j], acc[i][j]);
        }
        __syncthreads();
    }

#pragma unroll
    for (int i = 0; i < 8; i++) {
        const int gm = bm + ty * 8 + i;
#pragma unroll
        for (int j = 0; j < 8; j++) {
            const int gn = bn + tx * 8 + j;
            const float v = acc[i][j] + bias[gn];
            if (mode == 0) {
                C[(size_t)gm * D_ + gn] = v;
            } else {
                const int b  = gm >> 11;      // / S_
                const int s  = gm & (S_ - 1);
                const int h  = gn >> 6;       // / HD_
                const int hd = gn & (HD_ - 1);
                C[((((size_t)b * H_ + h) * S_ + s) << 6) + hd] = v;
            }
        }
    }
}

// ---------------------------------------------------------------------------
// Flash attention, fp32. One CTA = (b,h) x 128 query rows; 1 thread = 1 query.
// Q row + 64-float accumulator in registers; K/V staged in smem in 64-key
// tiles, read via broadcast LDS.128. Online softmax with conditional rescale.
// Output written in [B, S, D] layout (ready for output projection).
// ---------------------------------------------------------------------------
__global__ __launch_bounds__(128) void attn_kernel(
    const float* __restrict__ Q, const float* __restrict__ Kg,
    const float* __restrict__ Vg, float* __restrict__ O)
{
    __shared__ float sK[64 * HD_];
    __shared__ float sV[64 * HD_];

    const int bh = blockIdx.y;          // 0..63
    const int b  = bh >> 4;             // / H_
    const int t  = threadIdx.x;
    const int qrow = blockIdx.x * 128 + t;

    const float* qp = Q + ((size_t)bh * S_ + qrow) * HD_;
    float4 q4[16];
#pragma unroll
    for (int i = 0; i < 16; i++) q4[i] = ((const float4*)qp)[i];

    float4 acc[16];
#pragma unroll
    for (int i = 0; i < 16; i++) acc[i] = make_float4(0.f, 0.f, 0.f, 0.f);

    float mmax = -INFINITY;
    float l = 0.f;
    const float scale = 0.125f;  // HD_^-0.5

    const float* kbase = Kg + (size_t)bh * S_ * HD_;
    const float* vbase = Vg + (size_t)bh * S_ * HD_;

    for (int k0 = 0; k0 < S_; k0 += 64) {
        // cooperative tile load: 64*64 floats = 1024 float4, 128 threads x 8
        const float4* ksrc = (const float4*)(kbase + (size_t)k0 * HD_);
        const float4* vsrc = (const float4*)(vbase + (size_t)k0 * HD_);
        float4* dk = (float4*)sK;
        float4* dv = (float4*)sV;
#pragma unroll
        for (int i = 0; i < 8; i++) {
            dk[t + i * 128] = ksrc[t + i * 128];
            dv[t + i * 128] = vsrc[t + i * 128];
        }
        __syncthreads();

#pragma unroll 2
        for (int j = 0; j < 64; j++) {
            const float4* kr = (const float4*)(sK + j * HD_);
            float s0 = 0.f, s1 = 0.f, s2 = 0.f, s3 = 0.f;
#pragma unroll
            for (int i = 0; i < 16; i++) {
                float4 kv = kr[i];
                s0 = fmaf(q4[i].x, kv.x, s0);
                s1 = fmaf(q4[i].y, kv.y, s1);
                s2 = fmaf(q4[i].z, kv.z, s2);
                s3 = fmaf(q4[i].w, kv.w, s3);
            }
            float s = ((s0 + s1) + (s2 + s3)) * scale;

            if (s > mmax) {
                const float corr = __expf(mmax - s);  // exp(-inf)=0 on first key
                mmax = s;
                l *= corr;
#pragma unroll
                for (int i = 0; i < 16; i++) {
                    acc[i].x *= corr; acc[i].y *= corr;
                    acc[i].z *= corr; acc[i].w *= corr;
                }
            }
            const float p = __expf(s - mmax);
            l += p;

            const float4* vr = (const float4*)(sV + j * HD_);
#pragma unroll
            for (int i = 0; i < 16; i++) {
                float4 vv = vr[i];
                acc[i].x = fmaf(p, vv.x, acc[i].x);
                acc[i].y = fmaf(p, vv.y, acc[i].y);
                acc[i].z = fmaf(p, vv.z, acc[i].z);
                acc[i].w = fmaf(p, vv.w, acc[i].w);
            }
        }
        __syncthreads();
    }

    const float inv = 1.f / l;
    const int h = bh & (H_ - 1);
    float* op = O + ((size_t)(b * S_ + qrow)) * D_ + h * HD_;
#pragma unroll
    for (int i = 0; i < 16; i++) {
        float4 o;
        o.x = acc[i].x * inv; o.y = acc[i].y * inv;
        o.z = acc[i].z * inv; o.w = acc[i].w * inv;
        ((float4*)op)[i] = o;
    }
}

// ---------------------------------------------------------------------------
extern "C" void kernel_launch(void* const* d_in, const int* in_sizes, int n_in,
                              void* d_out, int out_size)
{
    const float* x  = (const float*)d_in[0];
    const float* wq = (const float*)d_in[1];
    const float* bq = (const float*)d_in[2];
    const float* wk = (const float*)d_in[3];
    const float* bk = (const float*)d_in[4];
    const float* wv = (const float*)d_in[5];
    const float* bv = (const float*)d_in[6];
    const float* wo = (const float*)d_in[7];
    const float* bo = (const float*)d_in[8];
    float* out = (float*)d_out;

    float *q, *k, *v, *ao;
    cudaGetSymbolAddress((void**)&q,  g_q);
    cudaGetSymbolAddress((void**)&k,  g_k);
    cudaGetSymbolAddress((void**)&v,  g_v);
    cudaGetSymbolAddress((void**)&ao, g_ao);

    dim3 ggrid(D_ / 128, M_ / 128);   // (8, 64)
    gemm_nt<<<ggrid, 256>>>(x, wq, bq, q, 1);
    gemm_nt<<<ggrid, 256>>>(x, wk, bk, k, 1);
    gemm_nt<<<ggrid, 256>>>(x, wv, bv, v, 1);

    dim3 agrid(S_ / 128, B_ * H_);    // (16, 64)
    attn_kernel<<<agrid, 128>>>(q, k, v, ao);

    gemm_nt<<<ggrid, 256>>>(ao, wo, bo, out, 0);
}